// round 4
// baseline (speedup 1.0000x reference)
#include <cuda_runtime.h>
#include <math.h>

#define B_  16
#define L_  4096
#define E_  128
#define F_  256
#define Y_  1000
#define MP_ 2048             /* padded attn M (2000 -> 2048) */

#define BM   128
#define BN   128
#define BKC  32              /* K chunk (fp32 elems) */
#define SROW 36              /* smem row stride in words (bank-conflict-free frags) */
#define STAGE_W (BM * SROW)  /* words per stage per matrix = 4608 */
#define SMEM_BYTES (4 * STAGE_W * 4)   /* A0,A1,B0,B1 = 73728 B */

// Scratch (static __device__ arrays; allocation-free per harness rules)
__device__ __align__(128) float g_embT[(size_t)B_ * L_ * E_];   // tf32-rounded embeddings
__device__ __align__(128) float g_wT  [3 * F_ * E_];            // tf32-rounded conv_w [kw][f][e]
__device__ __align__(128) float g_w2  [(size_t)MP_ * F_];       // tf32-rounded [U_w;fc_w;0pad]
__device__ __align__(128) float g_hcT [(size_t)B_ * L_ * F_];   // conv out (tf32-rounded), [b][l][f]
__device__ __align__(128) float g_st  [(size_t)B_ * MP_ * L_];  // scores rows [0,1000), t rows [1000,2000)

// ---------------------------------------------------------------------------
__device__ __forceinline__ float to_tf32f(float x) {
    unsigned r;
    asm("cvt.rna.tf32.f32 %0, %1;" : "=r"(r) : "f"(x));
    return __uint_as_float(r);
}
__device__ __forceinline__ void mma_tf32(float* d, const unsigned* a, const unsigned* b) {
    asm volatile(
        "mma.sync.aligned.m16n8k8.row.col.f32.tf32.tf32.f32 "
        "{%0,%1,%2,%3}, {%4,%5,%6,%7}, {%8,%9}, {%0,%1,%2,%3};"
        : "+f"(d[0]), "+f"(d[1]), "+f"(d[2]), "+f"(d[3])
        : "r"(a[0]), "r"(a[1]), "r"(a[2]), "r"(a[3]), "r"(b[0]), "r"(b[1]));
}
__device__ __forceinline__ unsigned smem_u32(const void* p) {
    unsigned a;
    asm("{ .reg .u64 t; cvta.to.shared.u64 t, %1; cvt.u32.u64 %0, t; }"
        : "=r"(a) : "l"(p));
    return a;
}
__device__ __forceinline__ void cp_async16(unsigned dst, const void* src, int src_bytes) {
    asm volatile("cp.async.cg.shared.global [%0], [%1], 16, %2;"
                 :: "r"(dst), "l"(src), "r"(src_bytes));
}
__device__ __forceinline__ void cp_commit() {
    asm volatile("cp.async.commit_group;");
}

// ---------------------------------------------------------------------------
// Kernel 1: embedding gather (tf32-rounded): embT[b][l][e] = rna(embed_w[x[b][l]][e])
// ---------------------------------------------------------------------------
__global__ void embed_kernel(const int* __restrict__ x,
                             const float* __restrict__ embed_w)
{
    int b = blockIdx.y;
    int l = blockIdx.x * 8 + (threadIdx.x >> 5);
    int q = threadIdx.x & 31;
    int xi = x[b * L_ + l];
    float4 v = ((const float4*)(embed_w + (size_t)xi * E_))[q];
    v.x = to_tf32f(v.x); v.y = to_tf32f(v.y);
    v.z = to_tf32f(v.z); v.w = to_tf32f(v.w);
    ((float4*)(g_embT + ((size_t)b * L_ + l) * E_))[q] = v;
}

// ---------------------------------------------------------------------------
// Kernel 2: conv_w transpose+round (F,E,3) -> wT[kw][f][e];  and weight stack prep
// ---------------------------------------------------------------------------
__global__ void wtrans_kernel(const float* __restrict__ conv_w)
{
    int i = blockIdx.x * 256 + threadIdx.x;
    if (i < F_ * E_) {
        int f = i / E_, e = i % E_;
        #pragma unroll
        for (int kw = 0; kw < 3; kw++)
            g_wT[((size_t)kw * F_ + f) * E_ + e] =
                to_tf32f(conv_w[((size_t)f * E_ + e) * 3 + kw]);
    }
}

__global__ void wstack_kernel(const float* __restrict__ U_w,
                              const float* __restrict__ fc_w)
{
    int i = blockIdx.x * 256 + threadIdx.x;   // over MP_*F_/4
    int r = i / (F_ / 4), c4 = i % (F_ / 4);
    float4 v = make_float4(0.f, 0.f, 0.f, 0.f);
    if (r < Y_)          v = ((const float4*)(U_w  + (size_t)r * F_))[c4];
    else if (r < 2 * Y_) v = ((const float4*)(fc_w + (size_t)(r - Y_) * F_))[c4];
    v.x = to_tf32f(v.x); v.y = to_tf32f(v.y);
    v.z = to_tf32f(v.z); v.w = to_tf32f(v.w);
    ((float4*)(g_w2 + (size_t)r * F_))[c4] = v;
}

// ---------------------------------------------------------------------------
// Kernel 3/4: tf32 mma.sync GEMM with cp.async 2-stage pipeline.
// C[128,128] tile, 256 threads (8 warps, 4(M) x 2(N), warp tile 32x64).
// mode 0 (conv): C[l, f] = sum_kw sum_e embT[l+kw-1, e] * wT[kw][f][e]
//                K = 3*128 (12 chunks), +bias, relu, tf32-round -> g_hcT
// mode 1 (attn): C[m, l] = w2[m,:] . hcT[l,:]   K = 256 (8 chunks) -> g_st
// ---------------------------------------------------------------------------
__global__ __launch_bounds__(256)
void mma_gemm_kernel(const float* __restrict__ bias, int mode)
{
    extern __shared__ __align__(16) char smem[];
    unsigned* Sa[2];
    unsigned* Sb[2];
    Sa[0] = (unsigned*)smem;
    Sa[1] = Sa[0] + STAGE_W;
    Sb[0] = Sa[1] + STAGE_W;
    Sb[1] = Sb[0] + STAGE_W;
    unsigned sbase = smem_u32(smem);

    int tid  = threadIdx.x;
    int wid  = tid >> 5, lane = tid & 31;
    int g    = lane >> 2, tig = lane & 3;
    int wm   = wid >> 1,  wn  = wid & 1;       // warp coords: 4 x 2
    int b    = blockIdx.z;

    int m0, n0, nchunks;
    if (mode == 0) { m0 = blockIdx.x * BM; n0 = blockIdx.y * BN; nchunks = 12; }
    else           { m0 = blockIdx.y * BM; n0 = blockIdx.x * BN; nchunks = 8;  }

    // loader mapping: 2 threads per 32-float row-chunk, 4x 16B each
    int lrow = tid >> 1;
    int lcol = (tid & 1) * 16;

    float d[2][8][4];
    #pragma unroll
    for (int mi = 0; mi < 2; mi++)
        #pragma unroll
        for (int ni = 0; ni < 8; ni++)
            #pragma unroll
            for (int q = 0; q < 4; q++) d[mi][ni][q] = 0.0f;

    // ---- prefetch lambda (macro-style) ----
    auto prefetch = [&](int c) {
        int st = c & 1;
        const float* ap;
        const float* bp;
        int abytes = 16;
        if (mode == 0) {
            int kw = c >> 2, ks = c & 3;
            int lsrc = m0 + lrow + kw - 1;
            bool av = (lsrc >= 0 && lsrc < L_);
            abytes = av ? 16 : 0;
            ap = g_embT + ((size_t)b * L_ + (av ? lsrc : 0)) * E_ + ks * BKC + lcol;
            bp = g_wT + ((size_t)kw * F_ + n0 + lrow) * E_ + ks * BKC + lcol;
        } else {
            ap = g_w2  + (size_t)(m0 + lrow) * F_ + c * BKC + lcol;
            bp = g_hcT + ((size_t)b * L_ + n0 + lrow) * F_ + c * BKC + lcol;
        }
        unsigned da = sbase + (st * STAGE_W + lrow * SROW + lcol) * 4;
        unsigned db = sbase + ((2 + st) * STAGE_W + lrow * SROW + lcol) * 4;
        #pragma unroll
        for (int j = 0; j < 4; j++) {
            cp_async16(da + j * 16, ap + j * 4, abytes);
            cp_async16(db + j * 16, bp + j * 4, 16);
        }
    };

    prefetch(0);
    cp_commit();

    for (int c = 0; c < nchunks; c++) {
        if (c + 1 < nchunks) {
            prefetch(c + 1);
            cp_commit();
            asm volatile("cp.async.wait_group 1;");
        } else {
            asm volatile("cp.async.wait_group 0;");
        }
        __syncthreads();

        const unsigned* As = Sa[c & 1];
        const unsigned* Bs = Sb[c & 1];

        #pragma unroll
        for (int ks = 0; ks < 4; ks++) {
            int k8 = ks * 8;
            unsigned af[2][4];
            #pragma unroll
            for (int mi = 0; mi < 2; mi++) {
                int r = wm * 32 + mi * 16 + g;
                af[mi][0] = As[r * SROW + k8 + tig];
                af[mi][1] = As[(r + 8) * SROW + k8 + tig];
                af[mi][2] = As[r * SROW + k8 + tig + 4];
                af[mi][3] = As[(r + 8) * SROW + k8 + tig + 4];
            }
            unsigned bf[8][2];
            #pragma unroll
            for (int ni = 0; ni < 8; ni++) {
                int nb = wn * 64 + ni * 8 + g;
                bf[ni][0] = Bs[nb * SROW + k8 + tig];
                bf[ni][1] = Bs[nb * SROW + k8 + tig + 4];
            }
            #pragma unroll
            for (int mi = 0; mi < 2; mi++)
                #pragma unroll
                for (int ni = 0; ni < 8; ni++)
                    mma_tf32(d[mi][ni], af[mi], bf[ni]);
        }
        __syncthreads();
    }

    // ---- epilogue ----
    #pragma unroll
    for (int mi = 0; mi < 2; mi++) {
        int row = m0 + wm * 32 + mi * 16 + g;
        #pragma unroll
        for (int ni = 0; ni < 8; ni++) {
            int col = n0 + wn * 64 + ni * 8 + tig * 2;
            if (mode == 0) {
                float b0 = bias[col], b1 = bias[col + 1];
                float* p0 = g_hcT + ((size_t)b * L_ + row) * F_ + col;
                float* p1 = g_hcT + ((size_t)b * L_ + row + 8) * F_ + col;
                *(float2*)p0 = make_float2(to_tf32f(fmaxf(d[mi][ni][0] + b0, 0.f)),
                                           to_tf32f(fmaxf(d[mi][ni][1] + b1, 0.f)));
                *(float2*)p1 = make_float2(to_tf32f(fmaxf(d[mi][ni][2] + b0, 0.f)),
                                           to_tf32f(fmaxf(d[mi][ni][3] + b1, 0.f)));
            } else {
                float* p0 = g_st + ((size_t)b * MP_ + row) * L_ + col;
                float* p1 = g_st + ((size_t)b * MP_ + row + 8) * L_ + col;
                *(float2*)p0 = make_float2(d[mi][ni][0], d[mi][ni][1]);
                *(float2*)p1 = make_float2(d[mi][ni][2], d[mi][ni][3]);
            }
        }
    }
}

// ---------------------------------------------------------------------------
// Kernel 5: per-(b,y) online softmax over L + weighted sum of t -> logit.
// ---------------------------------------------------------------------------
__global__ void attn_reduce_kernel(const float* __restrict__ fc_b,
                                   float* __restrict__ out_logit)
{
    int y = blockIdx.x;
    int b = blockIdx.y;
    const float4* s4 = (const float4*)(g_st + ((size_t)b * MP_ + y) * L_);
    const float4* t4 = (const float4*)(g_st + ((size_t)b * MP_ + Y_ + y) * L_);

    float m = -1e30f, Z = 0.0f, S = 0.0f;
    for (int i = threadIdx.x; i < L_ / 4; i += blockDim.x) {
        float4 sv = s4[i];
        float4 tv = t4[i];
        float svv[4] = {sv.x, sv.y, sv.z, sv.w};
        float tvv[4] = {tv.x, tv.y, tv.z, tv.w};
        #pragma unroll
        for (int u = 0; u < 4; u++) {
            float s_ = svv[u];
            if (s_ > m) {
                float r = expf(m - s_);
                Z *= r; S *= r; m = s_;
            }
            float e = expf(s_ - m);
            Z += e; S += e * tvv[u];
        }
    }
    #pragma unroll
    for (int off = 16; off; off >>= 1) {
        float m2 = __shfl_xor_sync(0xFFFFFFFFu, m, off);
        float Z2 = __shfl_xor_sync(0xFFFFFFFFu, Z, off);
        float S2 = __shfl_xor_sync(0xFFFFFFFFu, S, off);
        float mn = fmaxf(m, m2);
        float r1 = expf(m - mn), r2 = expf(m2 - mn);
        Z = Z * r1 + Z2 * r2;
        S = S * r1 + S2 * r2;
        m = mn;
    }
    __shared__ float sm[8], sz[8], ss[8];
    int lane = threadIdx.x & 31, w = threadIdx.x >> 5;
    if (lane == 0) { sm[w] = m; sz[w] = Z; ss[w] = S; }
    __syncthreads();
    if (threadIdx.x == 0) {
        m = sm[0]; Z = sz[0]; S = ss[0];
        int nw = blockDim.x >> 5;
        for (int i = 1; i < nw; i++) {
            float mn = fmaxf(m, sm[i]);
            float r1 = expf(m - mn), r2 = expf(sm[i] - mn);
            Z = Z * r1 + sz[i] * r2;
            S = S * r1 + ss[i] * r2;
            m = mn;
        }
        out_logit[b * Y_ + y] = S / Z + fc_b[y];
    }
}

// ---------------------------------------------------------------------------
// Kernel 6: cross-entropy loss
// ---------------------------------------------------------------------------
__global__ void loss_kernel(const float* __restrict__ logit,
                            const int* __restrict__ target,
                            float* __restrict__ loss_out)
{
    __shared__ float red[256];
    int tid = threadIdx.x;
    float total = 0.0f;
    for (int b = 0; b < B_; b++) {
        const float* lr = logit + b * Y_;
        float mx = -1e30f;
        for (int i = tid; i < Y_; i += 256) mx = fmaxf(mx, lr[i]);
        red[tid] = mx; __syncthreads();
        for (int s = 128; s; s >>= 1) {
            if (tid < s) red[tid] = fmaxf(red[tid], red[tid + s]);
            __syncthreads();
        }
        mx = red[0]; __syncthreads();

        float se = 0.0f;
        for (int i = tid; i < Y_; i += 256) se += expf(lr[i] - mx);
        red[tid] = se; __syncthreads();
        for (int s = 128; s; s >>= 1) {
            if (tid < s) red[tid] += red[tid + s];
            __syncthreads();
        }
        if (tid == 0) {
            float lp = lr[target[b]] - mx - logf(red[0]);
            total += -lp;
        }
        __syncthreads();
    }
    if (tid == 0) loss_out[0] = total / (float)B_;
}

// ---------------------------------------------------------------------------
extern "C" void kernel_launch(void* const* d_in, const int* in_sizes, int n_in,
                              void* d_out, int out_size)
{
    const int*   x       = (const int*)  d_in[0];
    const int*   target  = (const int*)  d_in[1];
    const float* embed_w = (const float*)d_in[2];
    const float* conv_w  = (const float*)d_in[3];
    const float* conv_b  = (const float*)d_in[4];
    const float* U_w     = (const float*)d_in[5];
    const float* fc_w    = (const float*)d_in[6];
    const float* fc_b    = (const float*)d_in[7];
    float* out = (float*)d_out;   // [0..15999] logits, [16000] loss

    static int smem_set = 0;
    if (!smem_set) {
        cudaFuncSetAttribute(mma_gemm_kernel,
                             cudaFuncAttributeMaxDynamicSharedMemorySize, SMEM_BYTES);
        smem_set = 1;
    }

    // 1) producers: rounded embeddings + weights
    embed_kernel<<<dim3(L_ / 8, B_), 256>>>(x, embed_w);
    wtrans_kernel<<<(F_ * E_ + 255) / 256, 256>>>(conv_w);
    wstack_kernel<<<(MP_ * F_ / 4 + 255) / 256, 256>>>(U_w, fc_w);

    // 2) conv as 3 shifted K=128 GEMMs
    mma_gemm_kernel<<<dim3(L_ / BM, F_ / BN, B_), 256, SMEM_BYTES>>>(
        conv_b, /*mode=*/0);

    // 3) attn GEMM: st[b][m][l] = w2 . hcT^T
    mma_gemm_kernel<<<dim3(L_ / BN, MP_ / BM, B_), 256, SMEM_BYTES>>>(
        nullptr, /*mode=*/1);

    // 4) softmax-attend reduction -> logits
    attn_reduce_kernel<<<dim3(Y_, B_), 256>>>(fc_b, out);

    // 5) cross-entropy loss
    loss_kernel<<<1, 256>>>(out, target, out + B_ * Y_);
}

// round 5
// speedup vs baseline: 2.0642x; 2.0642x over previous
#include <cuda_runtime.h>
#include <cuda_fp16.h>
#include <math.h>

#define B_  16
#define L_  4096
#define E_  128
#define F_  256
#define Y_  1000
#define YP_ 1024
#define MP_ 2048             /* padded, interleaved attn M */

#define BM  128
#define BN  128
#define BK  32               /* halves per K chunk */
#define SROWH 40             /* smem row stride in halves (80B) */
#define STAGEH (BM * SROWH)  /* halves per stage per matrix */

// Scratch (static __device__ arrays; allocation-free per harness rules)
__device__ __align__(128) __half g_embH[(size_t)B_ * L_ * E_];  // fp16 embeddings
__device__ __align__(128) __half g_wH  [3 * F_ * E_];           // fp16 conv_w [kw][f][e]
__device__ __align__(128) __half g_w2H [(size_t)MP_ * F_];      // interleaved [U;fc] rows
__device__ __align__(128) __half g_hcH [(size_t)B_ * L_ * F_];  // conv out fp16 [b][l][f]
__device__ __align__(128) float  g_part[(size_t)B_ * YP_ * 64 * 3]; // (m,Z,S) partials

// ---------------------------------------------------------------------------
__device__ __forceinline__ unsigned smem_u32(const void* p) {
    unsigned a;
    asm("{ .reg .u64 t; cvta.to.shared.u64 t, %1; cvt.u32.u64 %0, t; }"
        : "=r"(a) : "l"(p));
    return a;
}
__device__ __forceinline__ void cp_async16(unsigned dst, const void* src, int src_bytes) {
    asm volatile("cp.async.cg.shared.global [%0], [%1], 16, %2;"
                 :: "r"(dst), "l"(src), "r"(src_bytes));
}
__device__ __forceinline__ void cp_commit() {
    asm volatile("cp.async.commit_group;");
}
__device__ __forceinline__ void ldsm4(unsigned* r, unsigned addr) {
    asm volatile("ldmatrix.sync.aligned.m8n8.x4.shared.b16 {%0,%1,%2,%3}, [%4];"
                 : "=r"(r[0]), "=r"(r[1]), "=r"(r[2]), "=r"(r[3]) : "r"(addr));
}
__device__ __forceinline__ void mma16816(float* d, const unsigned* a, const unsigned* b) {
    asm volatile(
        "mma.sync.aligned.m16n8k16.row.col.f32.f16.f16.f32 "
        "{%0,%1,%2,%3}, {%4,%5,%6,%7}, {%8,%9}, {%0,%1,%2,%3};"
        : "+f"(d[0]), "+f"(d[1]), "+f"(d[2]), "+f"(d[3])
        : "r"(a[0]), "r"(a[1]), "r"(a[2]), "r"(a[3]), "r"(b[0]), "r"(b[1]));
}

// ---------------------------------------------------------------------------
// Kernel 1: embedding gather -> fp16: embH[b][l][e] = rn(embed_w[x[b][l]][e])
// ---------------------------------------------------------------------------
__global__ void embed_kernel(const int* __restrict__ x,
                             const float* __restrict__ embed_w)
{
    int b = blockIdx.y;
    int l = blockIdx.x * 8 + (threadIdx.x >> 5);
    int q = threadIdx.x & 31;
    int xi = x[b * L_ + l];
    float4 v = ((const float4*)(embed_w + (size_t)xi * E_))[q];
    __half2 h01 = __floats2half2_rn(v.x, v.y);
    __half2 h23 = __floats2half2_rn(v.z, v.w);
    uint2 u;
    u.x = *(unsigned*)&h01;
    u.y = *(unsigned*)&h23;
    ((uint2*)(g_embH + ((size_t)b * L_ + l) * E_))[q] = u;
}

// ---------------------------------------------------------------------------
// Kernel 2a: conv_w transpose+round (F,E,3) -> wH[kw][f][e]
// ---------------------------------------------------------------------------
__global__ void wtrans_kernel(const float* __restrict__ conv_w)
{
    int i = blockIdx.x * 256 + threadIdx.x;
    if (i < F_ * E_) {
        int f = i / E_, e = i % E_;
        #pragma unroll
        for (int kw = 0; kw < 3; kw++)
            g_wH[((size_t)kw * F_ + f) * E_ + e] =
                __float2half_rn(conv_w[((size_t)f * E_ + e) * 3 + kw]);
    }
}

// ---------------------------------------------------------------------------
// Kernel 2b: interleaved weight stack: row 2y = U_w[y], row 2y+1 = fc_w[y]
// ---------------------------------------------------------------------------
__global__ void wstack_kernel(const float* __restrict__ U_w,
                              const float* __restrict__ fc_w)
{
    int i = blockIdx.x * 256 + threadIdx.x;   // over MP_*F_/4
    if (i >= MP_ * F_ / 4) return;
    int r = i / (F_ / 4), c4 = i % (F_ / 4);
    float4 v = make_float4(0.f, 0.f, 0.f, 0.f);
    if (r < 2 * Y_) {
        int y = r >> 1;
        const float* src = (r & 1) ? fc_w : U_w;
        v = ((const float4*)(src + (size_t)y * F_))[c4];
    }
    __half2 h01 = __floats2half2_rn(v.x, v.y);
    __half2 h23 = __floats2half2_rn(v.z, v.w);
    uint2 u;
    u.x = *(unsigned*)&h01;
    u.y = *(unsigned*)&h23;
    ((uint2*)(g_w2H + (size_t)r * F_))[c4] = u;
}

// ---------------------------------------------------------------------------
// Kernel 3/4: fp16 m16n8k16 GEMM, 128x128 tile, 8 warps (4M x 2N), wtile 32x64.
// mode 0 (conv): C[l,f] = sum_kw sum_e embH[l+kw-1,e]*wH[kw][f][e]; +bias,relu -> hcH
// mode 1 (attn): C[m,l] = w2H[m,:] . hcH[l,:]; fused online-softmax partials
// ---------------------------------------------------------------------------
__global__ __launch_bounds__(256)
void hgemm_kernel(const float* __restrict__ bias, int mode)
{
    __shared__ __align__(16) __half sA[2 * STAGEH];
    __shared__ __align__(16) __half sB[2 * STAGEH];
    unsigned aBase = smem_u32(sA);
    unsigned bBase = smem_u32(sB);

    int tid  = threadIdx.x;
    int wid  = tid >> 5, lane = tid & 31;
    int g    = lane >> 2, tig = lane & 3;
    int lq   = lane >> 3, lr  = lane & 7;      // ldmatrix quad / row
    int wm   = wid >> 1,  wn  = wid & 1;
    int b    = blockIdx.z;

    int m0, n0, nchunks;
    if (mode == 0) { m0 = blockIdx.x * BM; n0 = blockIdx.y * BN; nchunks = 12; }
    else           { m0 = blockIdx.y * BM; n0 = blockIdx.x * BN; nchunks = 8;  }

    // loader: 2 threads per row, 2 x 16B each (32 halves/row)
    int lrow  = tid >> 1;
    int lcolh = (tid & 1) * 16;

    float d[2][8][4];
    #pragma unroll
    for (int mi = 0; mi < 2; mi++)
        #pragma unroll
        for (int ni = 0; ni < 8; ni++)
            #pragma unroll
            for (int q = 0; q < 4; q++) d[mi][ni][q] = 0.0f;

    auto prefetch = [&](int c) {
        int st = c & 1;
        const __half* ap;
        const __half* bp;
        int abytes = 16;
        if (mode == 0) {
            int kw = c >> 2, ks = c & 3;
            int lsrc = m0 + lrow + kw - 1;
            bool av = ((unsigned)lsrc < (unsigned)L_);
            abytes = av ? 16 : 0;
            ap = g_embH + ((size_t)b * L_ + (av ? lsrc : 0)) * E_ + ks * BK + lcolh;
            bp = g_wH + ((size_t)kw * F_ + n0 + lrow) * E_ + ks * BK + lcolh;
        } else {
            ap = g_w2H + (size_t)(m0 + lrow) * F_ + c * BK + lcolh;
            bp = g_hcH + ((size_t)b * L_ + n0 + lrow) * F_ + c * BK + lcolh;
        }
        unsigned da = aBase + (st * STAGEH + lrow * SROWH + lcolh) * 2;
        unsigned db = bBase + (st * STAGEH + lrow * SROWH + lcolh) * 2;
        cp_async16(da,      ap,     abytes);
        cp_async16(da + 16, ap + 8, abytes);
        cp_async16(db,      bp,     16);
        cp_async16(db + 16, bp + 8, 16);
    };

    prefetch(0);
    cp_commit();

    for (int c = 0; c < nchunks; c++) {
        if (c + 1 < nchunks) {
            prefetch(c + 1);
            cp_commit();
            asm volatile("cp.async.wait_group 1;");
        } else {
            asm volatile("cp.async.wait_group 0;");
        }
        __syncthreads();

        int st = c & 1;
        unsigned Ab = aBase + st * STAGEH * 2;
        unsigned Bb = bBase + st * STAGEH * 2;

        #pragma unroll
        for (int kk = 0; kk < 2; kk++) {
            unsigned af[2][4];
            #pragma unroll
            for (int mi = 0; mi < 2; mi++) {
                int row = wm * 32 + mi * 16 + (lq & 1) * 8 + lr;
                int col = kk * 16 + (lq >> 1) * 8;
                ldsm4(af[mi], Ab + (row * SROWH + col) * 2);
            }
            unsigned bf[4][4];
            #pragma unroll
            for (int ti = 0; ti < 4; ti++) {
                int row = wn * 64 + ti * 16 + (lq >> 1) * 8 + lr;
                int col = kk * 16 + (lq & 1) * 8;
                ldsm4(bf[ti], Bb + (row * SROWH + col) * 2);
            }
            #pragma unroll
            for (int mi = 0; mi < 2; mi++)
                #pragma unroll
                for (int ni = 0; ni < 8; ni++)
                    mma16816(d[mi][ni], af[mi], &bf[ni >> 1][(ni & 1) * 2]);
        }
        __syncthreads();
    }

    // ------------------------- epilogue ------------------------------------
    if (mode == 0) {
        #pragma unroll
        for (int mi = 0; mi < 2; mi++) {
            int row = m0 + wm * 32 + mi * 16 + g;
            #pragma unroll
            for (int ni = 0; ni < 8; ni++) {
                int col = n0 + wn * 64 + ni * 8 + tig * 2;
                float b0 = bias[col], b1 = bias[col + 1];
                __half2 v0 = __floats2half2_rn(fmaxf(d[mi][ni][0] + b0, 0.f),
                                               fmaxf(d[mi][ni][1] + b1, 0.f));
                __half2 v1 = __floats2half2_rn(fmaxf(d[mi][ni][2] + b0, 0.f),
                                               fmaxf(d[mi][ni][3] + b1, 0.f));
                *(__half2*)(g_hcH + ((size_t)b * L_ + row) * F_ + col)     = v0;
                *(__half2*)(g_hcH + ((size_t)b * L_ + row + 8) * F_ + col) = v1;
            }
        }
    } else {
        // rows interleaved: even m = s (U_w), odd m = t (fc_w). Thread rows have
        // parity of g; t for s-row r lives at row r+1 = lane+4's fragment.
        int p = blockIdx.x * 2 + wn;        // 64-l chunk index (0..63)
        #pragma unroll
        for (int mi = 0; mi < 2; mi++) {
            float td[8][4];
            #pragma unroll
            for (int ni = 0; ni < 8; ni++)
                #pragma unroll
                for (int q = 0; q < 4; q++)
                    td[ni][q] = __shfl_down_sync(0xFFFFFFFFu, d[mi][ni][q], 4);

            if ((g & 1) == 0) {
                #pragma unroll
                for (int h = 0; h < 2; h++) {
                    float mm = -1e30f, Z = 0.f, S = 0.f;
                    #pragma unroll
                    for (int ni = 0; ni < 8; ni++) {
                        #pragma unroll
                        for (int cq = 0; cq < 2; cq++) {
                            float sv = d[mi][ni][h * 2 + cq];
                            float tv = td[ni][h * 2 + cq];
                            if (sv > mm) {
                                float r = __expf(mm - sv);
                                Z *= r; S *= r; mm = sv;
                            }
                            float e = __expf(sv - mm);
                            Z += e; S += e * tv;
                        }
                    }
                    // reduce over the 4-lane quad (tig): lanes g*4..g*4+3
                    const unsigned qmask = 0x0F0F0F0Fu;
                    #pragma unroll
                    for (int off = 1; off <= 2; off <<= 1) {
                        float m2 = __shfl_xor_sync(qmask, mm, off);
                        float Z2 = __shfl_xor_sync(qmask, Z, off);
                        float S2 = __shfl_xor_sync(qmask, S, off);
                        float mn = fmaxf(mm, m2);
                        float r1 = __expf(mm - mn), r2 = __expf(m2 - mn);
                        Z = Z * r1 + Z2 * r2;
                        S = S * r1 + S2 * r2;
                        mm = mn;
                    }
                    if (tig == 0) {
                        int y = (m0 + wm * 32 + mi * 16 + g + 8 * h) >> 1;
                        float* dst = g_part + ((size_t)(b * YP_ + y) * 64 + p) * 3;
                        dst[0] = mm; dst[1] = Z; dst[2] = S;
                    }
                }
            }
        }
    }
}

// ---------------------------------------------------------------------------
// Kernel 5: merge 64 softmax partials per (b,y) -> logits
// ---------------------------------------------------------------------------
__global__ void part_reduce_kernel(const float* __restrict__ fc_b,
                                   float* __restrict__ out_logit)
{
    int idx = blockIdx.x;
    int b = idx / Y_, y = idx % Y_;
    const float* pp = g_part + ((size_t)(b * YP_ + y) * 64) * 3;
    int lane = threadIdx.x;

    float m = pp[lane * 3], Z = pp[lane * 3 + 1], S = pp[lane * 3 + 2];
    {
        float m2 = pp[(lane + 32) * 3], Z2 = pp[(lane + 32) * 3 + 1], S2 = pp[(lane + 32) * 3 + 2];
        float mn = fmaxf(m, m2);
        float r1 = __expf(m - mn), r2 = __expf(m2 - mn);
        Z = Z * r1 + Z2 * r2; S = S * r1 + S2 * r2; m = mn;
    }
    #pragma unroll
    for (int off = 16; off; off >>= 1) {
        float m2 = __shfl_xor_sync(0xFFFFFFFFu, m, off);
        float Z2 = __shfl_xor_sync(0xFFFFFFFFu, Z, off);
        float S2 = __shfl_xor_sync(0xFFFFFFFFu, S, off);
        float mn = fmaxf(m, m2);
        float r1 = __expf(m - mn), r2 = __expf(m2 - mn);
        Z = Z * r1 + Z2 * r2; S = S * r1 + S2 * r2; m = mn;
    }
    if (lane == 0) out_logit[b * Y_ + y] = S / Z + fc_b[y];
}

// ---------------------------------------------------------------------------
// Kernel 6: cross-entropy loss
// ---------------------------------------------------------------------------
__global__ void loss_kernel(const float* __restrict__ logit,
                            const int* __restrict__ target,
                            float* __restrict__ loss_out)
{
    __shared__ float red[256];
    int tid = threadIdx.x;
    float total = 0.0f;
    for (int b = 0; b < B_; b++) {
        const float* lr = logit + b * Y_;
        float mx = -1e30f;
        for (int i = tid; i < Y_; i += 256) mx = fmaxf(mx, lr[i]);
        red[tid] = mx; __syncthreads();
        for (int s = 128; s; s >>= 1) {
            if (tid < s) red[tid] = fmaxf(red[tid], red[tid + s]);
            __syncthreads();
        }
        mx = red[0]; __syncthreads();

        float se = 0.0f;
        for (int i = tid; i < Y_; i += 256) se += expf(lr[i] - mx);
        red[tid] = se; __syncthreads();
        for (int s = 128; s; s >>= 1) {
            if (tid < s) red[tid] += red[tid + s];
            __syncthreads();
        }
        if (tid == 0) {
            float lp = lr[target[b]] - mx - logf(red[0]);
            total += -lp;
        }
        __syncthreads();
    }
    if (tid == 0) loss_out[0] = total / (float)B_;
}

// ---------------------------------------------------------------------------
extern "C" void kernel_launch(void* const* d_in, const int* in_sizes, int n_in,
                              void* d_out, int out_size)
{
    const int*   x       = (const int*)  d_in[0];
    const int*   target  = (const int*)  d_in[1];
    const float* embed_w = (const float*)d_in[2];
    const float* conv_w  = (const float*)d_in[3];
    const float* conv_b  = (const float*)d_in[4];
    const float* U_w     = (const float*)d_in[5];
    const float* fc_w    = (const float*)d_in[6];
    const float* fc_b    = (const float*)d_in[7];
    float* out = (float*)d_out;   // [0..15999] logits, [16000] loss

    // 1) producers: fp16 embeddings + weights
    embed_kernel<<<dim3(L_ / 8, B_), 256>>>(x, embed_w);
    wtrans_kernel<<<(F_ * E_ + 255) / 256, 256>>>(conv_w);
    wstack_kernel<<<(MP_ * F_ / 4 + 255) / 256, 256>>>(U_w, fc_w);

    // 2) conv as 3 shifted K=128 GEMMs -> hcH (fp16)
    hgemm_kernel<<<dim3(L_ / BM, F_ / BN, B_), 256>>>(conv_b, /*mode=*/0);

    // 3) attn GEMM with fused softmax partials
    hgemm_kernel<<<dim3(L_ / BN, MP_ / BM, B_), 256>>>(nullptr, /*mode=*/1);

    // 4) merge partials -> logits
    part_reduce_kernel<<<B_ * Y_, 32>>>(fc_b, out);

    // 5) cross-entropy loss
    loss_kernel<<<1, 256>>>(out, target, out + B_ * Y_);
}